// round 2
// baseline (speedup 1.0000x reference)
#include <cuda_runtime.h>
#include <cstdint>

// Problem constants (fixed by setup_inputs)
#define C_    32
#define S_    9
#define H_    192
#define W_    256
#define G_    8
#define NSRC  8            // N-1 source images
#define TW    32           // pixels (w) per block tile
#define THREADS 256

#define WS    (W_*S_)      // 2304
#define HWS   (H_*WS)      // 442368
#define CHWS  (C_*HWS)     // 14155776
#define ROW   (TW*S_)      // 288 floats per channel per tile
#define F4ROW (ROW/4)      // 72 float4 per channel row
#define TILE_F4 (C_*F4ROW) // 2304 float4 per image-tile
#define ITERS (TILE_F4/THREADS) // 9 cp.async per thread per stage

// smem layout (floats)
#define OFF_REF   0
#define OFF_SRC0  9216
#define OFF_SRC1  18432
#define OFF_WPT   27648     // Wp transposed: WpT[c*32+d]
#define OFF_BP    28672
#define OFF_PC4   28704     // proj at s=4: pc4[d*32+w]
#define OFF_U     29728     // u[c*32+w]
#define OFF_ATT   30752     // att[w*9+s]
#define SMEM_FLOATS 31040
#define SMEM_BYTES  (SMEM_FLOATS*4)   // 124160

__device__ __forceinline__ void cp16(float* dst, const float4* src) {
    uint32_t s = (uint32_t)__cvta_generic_to_shared(dst);
    asm volatile("cp.async.cg.shared.global [%0], [%1], 16;\n" :: "r"(s), "l"(src));
}
__device__ __forceinline__ void cp_commit() {
    asm volatile("cp.async.commit_group;\n" ::);
}
__device__ __forceinline__ void cp_wait1() {
    asm volatile("cp.async.wait_group 1;\n" ::);
}
__device__ __forceinline__ void cp_wait0() {
    asm volatile("cp.async.wait_group 0;\n" ::);
}

__device__ __forceinline__ void stage_tile(float* dst, const float4* gbase) {
    // gbase points at the (image, h, w0) tile origin in float4 units.
    // smem float4 index j == c*F4ROW + k  (layout is identical to gmem chunk order)
    #pragma unroll
    for (int i = 0; i < ITERS; i++) {
        int j = threadIdx.x + i * THREADS;
        int c = j / F4ROW;
        int k = j - c * F4ROW;
        cp16(dst + j * 4, gbase + (size_t)c * (HWS >> 2) + k);
    }
    cp_commit();
}

__global__ __launch_bounds__(THREADS, 1)
void gcfs_kernel(const float* __restrict__ f,
                 const float* __restrict__ Wp,
                 const float* __restrict__ bp,
                 float* __restrict__ out) {
    extern __shared__ float sm[];
    float* refS = sm + OFF_REF;
    float* srcS0 = sm + OFF_SRC0;
    float* srcS1 = sm + OFF_SRC1;
    float* WpT  = sm + OFF_WPT;
    float* bpS  = sm + OFF_BP;
    float* pc4  = sm + OFF_PC4;
    float* uS   = sm + OFF_U;
    float* attS = sm + OFF_ATT;

    const int t  = threadIdx.x;
    const int h  = blockIdx.y;
    const int w0 = blockIdx.x * TW;

    const size_t tileOff = (size_t)h * WS + (size_t)w0 * S_;  // floats, %4==0
    const float4* fb4 = (const float4*)f;
    const size_t tile4 = tileOff >> 2;

    // --- stage ref (image 0): group 0 ---
    stage_tile(refS, fb4 + tile4);
    // --- stage src n=0 (image 1): group 1 ---
    stage_tile(srcS0, fb4 + (size_t)1 * (CHWS >> 2) + tile4);

    // Wp (transposed into smem) + bp, plain loads (small, L2-resident)
    for (int i = t; i < C_ * C_; i += THREADS) {
        int d = i >> 5, c = i & 31;
        WpT[c * 32 + d] = Wp[i];        // Wp row-major [d][c]
    }
    if (t < C_) bpS[t] = bp[t];

    cp_wait1();          // ref group done (src0 may still be in flight)
    __syncthreads();

    // --- step 1: pc4[d][w] = sum_c Wp[d,c]*ref[c,w,4] + bp[d] ---
    #pragma unroll
    for (int i = 0; i < 4; i++) {
        int item = t + i * THREADS;     // 1024 items
        int w = item & 31, d = item >> 5;
        float acc = bpS[d];
        #pragma unroll
        for (int c = 0; c < C_; c++)
            acc += WpT[c * 32 + d] * refS[c * ROW + w * S_ + 4];
        pc4[d * 32 + w] = acc;
    }
    __syncthreads();

    // --- step 2: u[c][w] = sum_d pc4[d][w]*Wp[d,c] ---
    #pragma unroll
    for (int i = 0; i < 4; i++) {
        int item = t + i * THREADS;
        int w = item & 31, c = item >> 5;
        float acc = 0.f;
        #pragma unroll
        for (int d = 0; d < C_; d++)
            acc += pc4[d * 32 + w] * WpT[c * 32 + d];
        uS[c * 32 + w] = acc;
    }
    __syncthreads();

    // --- step 3: logits + softmax (one warp; pixel per lane) ---
    if (t < TW) {
        const int w = t;
        float v = 0.f;
        #pragma unroll
        for (int d = 0; d < C_; d++) v += pc4[d * 32 + w] * bpS[d];

        float lg[S_];
        #pragma unroll
        for (int s = 0; s < S_; s++) {
            float a = v;
            #pragma unroll
            for (int c = 0; c < C_; c++)
                a += uS[c * 32 + w] * refS[c * ROW + w * S_ + s];
            lg[s] = a * 0.17677669529663687f;   // 1/sqrt(32)
        }
        float mx = lg[0];
        #pragma unroll
        for (int s = 1; s < S_; s++) mx = fmaxf(mx, lg[s]);
        float sum = 0.f;
        #pragma unroll
        for (int s = 0; s < S_; s++) { lg[s] = expf(lg[s] - mx); sum += lg[s]; }
        float inv = 1.f / sum;
        #pragma unroll
        for (int s = 0; s < S_; s++) attS[w * S_ + s] = lg[s] * inv;
    }
    __syncthreads();

    // --- main loop over source images, double-buffered ---
    const int w = t & 31;
    const int g = t >> 5;           // 8 groups x 32 pixels = 256 threads

    for (int n = 0; n < NSRC; n++) {
        if (n + 1 < NSRC) {
            float* dst = ((n + 1) & 1) ? srcS1 : srcS0;
            stage_tile(dst, fb4 + (size_t)(n + 2) * (CHWS >> 2) + tile4);
            cp_wait1();             // current buffer (group for n) complete
        } else {
            cp_wait0();
        }
        __syncthreads();

        const float* sb = (n & 1) ? srcS1 : srcS0;
        float acc = 0.f;
        #pragma unroll
        for (int s = 0; s < S_; s++) {
            float dot = 0.f;
            #pragma unroll
            for (int c = 0; c < 4; c++) {
                int cc = g * 4 + c;
                dot += refS[cc * ROW + w * S_ + s] * sb[cc * ROW + w * S_ + s];
            }
            acc += dot * attS[w * S_ + s];
        }
        out[(((size_t)n * G_ + g) * H_ + h) * W_ + w0 + w] = acc;
        __syncthreads();            // protect buffer reuse before next prefetch
    }
}

extern "C" void kernel_launch(void* const* d_in, const int* in_sizes, int n_in,
                              void* d_out, int out_size) {
    const float* f  = (const float*)d_in[0];
    const float* Wp = (const float*)d_in[1];
    const float* bp = (const float*)d_in[2];
    float* out = (float*)d_out;

    cudaFuncSetAttribute(gcfs_kernel,
                         cudaFuncAttributeMaxDynamicSharedMemorySize, SMEM_BYTES);
    dim3 grid(W_ / TW, H_);
    gcfs_kernel<<<grid, THREADS, SMEM_BYTES>>>(f, Wp, bp, out);
}

// round 3
// speedup vs baseline: 1.1605x; 1.1605x over previous
#include <cuda_runtime.h>
#include <cstdint>

// Problem constants (fixed by setup_inputs)
#define C_    32
#define S_    9
#define H_    192
#define W_    256
#define G_    8
#define NSRC  8            // N-1 source images
#define TW    16           // pixels (w) per block tile
#define THREADS 128

#define WS    (W_*S_)      // 2304
#define HWS   (H_*WS)      // 442368
#define CHWS  (C_*HWS)     // 14155776
#define ROW   (TW*S_)      // 144 floats per channel per tile
#define F4ROW (ROW/4)      // 36 float4 per channel row
#define TILE_F4 (C_*F4ROW) // 1152 float4 per image-tile
#define ITERS (TILE_F4/THREADS) // 9 cp.async per thread per stage

// smem layout (floats)
#define TILE_FLOATS (C_*ROW)       // 4608
#define OFF_REF   0
#define OFF_SRC0  (TILE_FLOATS)        // 4608
#define OFF_SRC1  (2*TILE_FLOATS)      // 9216
#define OFF_WPT   (3*TILE_FLOATS)      // 13824  Wp transposed: WpT[c*32+d]
#define OFF_BP    (OFF_WPT+1024)       // 14848
#define OFF_PC4   (OFF_BP+32)          // 14880  pc4[d*16+w]
#define OFF_U     (OFF_PC4+512)        // 15392  u[c*16+w]
#define OFF_ATT   (OFF_U+512)          // 15904  att[w*9+s]
#define SMEM_FLOATS (OFF_ATT+144)      // 16048
#define SMEM_BYTES  (SMEM_FLOATS*4)    // 64192  -> 3 blocks/SM

__device__ __forceinline__ void cp16(float* dst, const float4* src) {
    uint32_t s = (uint32_t)__cvta_generic_to_shared(dst);
    asm volatile("cp.async.cg.shared.global [%0], [%1], 16;\n" :: "r"(s), "l"(src));
}
__device__ __forceinline__ void cp_commit() {
    asm volatile("cp.async.commit_group;\n" ::);
}
__device__ __forceinline__ void cp_wait2() {
    asm volatile("cp.async.wait_group 2;\n" ::);
}
__device__ __forceinline__ void cp_wait1() {
    asm volatile("cp.async.wait_group 1;\n" ::);
}
__device__ __forceinline__ void cp_wait0() {
    asm volatile("cp.async.wait_group 0;\n" ::);
}

__device__ __forceinline__ void stage_tile(float* dst, const float4* gbase) {
    // gbase = (image, h, w0) tile origin in float4 units.
    // smem float4 index j == c*F4ROW + k (identical chunk order to gmem)
    #pragma unroll
    for (int i = 0; i < ITERS; i++) {
        int j = threadIdx.x + i * THREADS;
        int c = j / F4ROW;
        int k = j - c * F4ROW;
        cp16(dst + j * 4, gbase + (size_t)c * (HWS >> 2) + k);
    }
    cp_commit();
}

__global__ __launch_bounds__(THREADS)
void gcfs_kernel(const float* __restrict__ f,
                 const float* __restrict__ Wp,
                 const float* __restrict__ bp,
                 float* __restrict__ out) {
    extern __shared__ float sm[];
    float* refS  = sm + OFF_REF;
    float* srcS0 = sm + OFF_SRC0;
    float* srcS1 = sm + OFF_SRC1;
    float* WpT   = sm + OFF_WPT;
    float* bpS   = sm + OFF_BP;
    float* pc4   = sm + OFF_PC4;
    float* uS    = sm + OFF_U;
    float* attS  = sm + OFF_ATT;

    const int t  = threadIdx.x;
    const int h  = blockIdx.y;
    const int w0 = blockIdx.x * TW;

    const size_t tileOff = (size_t)h * WS + (size_t)w0 * S_;  // floats, %4==0
    const float4* fb4 = (const float4*)f;
    const size_t tile4 = tileOff >> 2;

    // --- prologue staging: ref, src0, src1 (3 cp.async groups) ---
    stage_tile(refS,  fb4 + tile4);
    stage_tile(srcS0, fb4 + (size_t)1 * (CHWS >> 2) + tile4);
    stage_tile(srcS1, fb4 + (size_t)2 * (CHWS >> 2) + tile4);

    // Wp (transposed) + bp via plain loads (tiny, L2-resident)
    for (int i = t; i < C_ * C_; i += THREADS) {
        int d = i >> 5, c = i & 31;
        WpT[c * 32 + d] = Wp[i];
    }
    if (t < C_) bpS[t] = bp[t];

    cp_wait2();          // ref complete; src0/src1 still streaming
    __syncthreads();

    // --- pc4[d][w] = sum_c Wp[d,c]*ref[c,w,4] + bp[d]  (512 items) ---
    #pragma unroll
    for (int i = 0; i < 4; i++) {
        int item = t + i * THREADS;
        int w = item & 15, d = item >> 4;
        float acc = bpS[d];
        #pragma unroll
        for (int c = 0; c < C_; c++)
            acc += WpT[c * 32 + d] * refS[c * ROW + w * S_ + 4];
        pc4[d * 16 + w] = acc;
    }
    __syncthreads();

    // --- u[c][w] = sum_d pc4[d][w]*Wp[d,c] ---
    #pragma unroll
    for (int i = 0; i < 4; i++) {
        int item = t + i * THREADS;
        int w = item & 15, c = item >> 4;
        float acc = 0.f;
        #pragma unroll
        for (int d = 0; d < C_; d++)
            acc += pc4[d * 16 + w] * WpT[c * 32 + d];
        uS[c * 16 + w] = acc;
    }
    __syncthreads();

    // --- logits + softmax (16 lanes; pixel per lane) ---
    if (t < TW) {
        const int w = t;
        float v = 0.f;
        #pragma unroll
        for (int d = 0; d < C_; d++) v += pc4[d * 16 + w] * bpS[d];

        float lg[S_];
        #pragma unroll
        for (int s = 0; s < S_; s++) {
            float a = v;
            #pragma unroll
            for (int c = 0; c < C_; c++)
                a += uS[c * 16 + w] * refS[c * ROW + w * S_ + s];
            lg[s] = a * 0.17677669529663687f;   // 1/sqrt(32)
        }
        float mx = lg[0];
        #pragma unroll
        for (int s = 1; s < S_; s++) mx = fmaxf(mx, lg[s]);
        float sum = 0.f;
        #pragma unroll
        for (int s = 0; s < S_; s++) { lg[s] = expf(lg[s] - mx); sum += lg[s]; }
        float inv = 1.f / sum;
        #pragma unroll
        for (int s = 0; s < S_; s++) attS[w * S_ + s] = lg[s] * inv;
    }
    __syncthreads();

    // --- hoist ref*att into registers: thread (g,w) owns 4 channels x 9 shifts ---
    const int w = t & 15;
    const int g = t >> 4;
    float rw[4][S_];
    #pragma unroll
    for (int c = 0; c < 4; c++) {
        #pragma unroll
        for (int s = 0; s < S_; s++)
            rw[c][s] = refS[(g * 4 + c) * ROW + w * S_ + s] * attS[w * S_ + s];
    }

    // --- main loop over source images, 2-deep ring x 3 resident blocks/SM ---
    float* const bufs[2] = { srcS0, srcS1 };
    #pragma unroll 1
    for (int n = 0; n < NSRC; n++) {
        if (n < NSRC - 1) cp_wait1(); else cp_wait0();   // src n complete
        __syncthreads();

        const float* sb = bufs[n & 1];
        float acc = 0.f;
        #pragma unroll
        for (int c = 0; c < 4; c++) {
            #pragma unroll
            for (int s = 0; s < S_; s++)
                acc += rw[c][s] * sb[(g * 4 + c) * ROW + w * S_ + s];
        }
        out[(((size_t)n * G_ + g) * H_ + h) * W_ + w0 + w] = acc;

        __syncthreads();            // all reads of buffer done before refill
        if (n + 2 < NSRC)
            stage_tile(bufs[n & 1], fb4 + (size_t)(n + 3) * (CHWS >> 2) + tile4);
    }
}

extern "C" void kernel_launch(void* const* d_in, const int* in_sizes, int n_in,
                              void* d_out, int out_size) {
    const float* f  = (const float*)d_in[0];
    const float* Wp = (const float*)d_in[1];
    const float* bp = (const float*)d_in[2];
    float* out = (float*)d_out;

    cudaFuncSetAttribute(gcfs_kernel,
                         cudaFuncAttributeMaxDynamicSharedMemorySize, SMEM_BYTES);
    dim3 grid(W_ / TW, H_);
    gcfs_kernel<<<grid, THREADS, SMEM_BYTES>>>(f, Wp, bp, out);
}